// round 9
// baseline (speedup 1.0000x reference)
#include <cuda_runtime.h>
#include <math.h>

#define CIN 32
#define COUT 64
#define WSTRIDE 4000

// Weight B-fragments prepacked in mma.m16n8k8 layout with PERMUTED cin<->k map:
// within kc-block of 8 cins, k -> cin_phys = 2*(k&3) + (k>=4).
// [tap(125)][kc(4)][ntp(4)][lane(32)] uint4 = (b0,b1 @ n-tile 2ntp, b0,b1 @ 2ntp+1)
__device__ uint4 g_bf[125 * 4 * 4 * 32];

__device__ __forceinline__ unsigned f2tf32(float v) {
    unsigned u;
    asm("cvt.rna.tf32.f32 %0, %1;" : "=r"(u) : "f"(v));
    return u;
}

__global__ void bf_pack_kernel(const float* __restrict__ w) {
    int i = blockIdx.x * blockDim.x + threadIdx.x;
    if (i >= 125 * 4 * 4 * 32) return;
    int lane = i & 31, ntp = (i >> 5) & 3, kc = (i >> 7) & 3, tap = i >> 9;
    int k = lane & 3, n = lane >> 2;
    int cinA = kc * 8 + 2 * k;
    int cinB = cinA + 1;
    int cout0 = (2 * ntp) * 8 + n, cout1 = cout0 + 8;
    uint4 o;
    o.x = f2tf32(w[(cinA * COUT + cout0) * 125 + tap]);
    o.y = f2tf32(w[(cinB * COUT + cout0) * 125 + tap]);
    o.z = f2tf32(w[(cinA * COUT + cout1) * 125 + tap]);
    o.w = f2tf32(w[(cinB * COUT + cout1) * 125 + tap]);
    g_bf[i] = o;
}

#define MMA(c0, c1, c2, c3, a0, a1, a2, a3, b0, b1)                              \
    asm("mma.sync.aligned.m16n8k8.row.col.f32.tf32.tf32.f32 "                    \
        "{%0,%1,%2,%3}, {%4,%5,%6,%7}, {%8,%9}, {%0,%1,%2,%3};"                  \
        : "+f"(c0), "+f"(c1), "+f"(c2), "+f"(c3)                                 \
        : "r"(a0), "r"(a1), "r"(a2), "r"(a3), "r"(b0), "r"(b1))

__device__ __forceinline__ int qoff(int pos) {      // pos in [0,27)
    int qd = pos / 9, qh = (pos / 3) % 3, qw = pos % 3;
    return qd * 25 + qh * 5 + qw;
}

// One (class, half) m-tile: compile-time parity (PD,PH,PW) -> fully unrolled
// taps with constant offsets. Accumulates into the per-warp running maxima.
template <int PD, int PH, int PW>
__device__ __forceinline__ void process_half(
    const float* __restrict__ xs, const int kb, const int lane,
    const int rr, const int half, float rmax[2][8][2])
{
    const int pos0 = half * 16 + rr;            // < 27 always
    const int pos1 = pos0 + 8;
    const bool v1  = (pos1 < 27);
    const int qo0 = 2 * qoff(pos0);
    const int qo1 = v1 ? 2 * qoff(pos1) : 0;

    float c[2][8][4];
#pragma unroll
    for (int w = 0; w < 2; ++w)
#pragma unroll
        for (int nt = 0; nt < 8; ++nt)
#pragma unroll
            for (int j = 0; j < 4; ++j) c[w][nt][j] = 0.f;

#pragma unroll
    for (int ia = 0; ia < (PD ? 2 : 3); ++ia) {
        const int kd = PD + 2 * ia, jd = 2 - ia;
#pragma unroll
        for (int ib = 0; ib < (PH ? 2 : 3); ++ib) {
            const int kh = PH + 2 * ib, jh = 2 - ib;
#pragma unroll
            for (int ic = 0; ic < (PW ? 2 : 3); ++ic) {
                const int kw = PW + 2 * ic, jw = 2 - ic;
                const int tap   = kd * 25 + kh * 5 + kw;        // compile-time
                const int jofs2 = 2 * (jd * 25 + jh * 5 + jw);  // compile-time
                const uint4* bp = g_bf + tap * 16 * 32 + lane;
#pragma unroll
                for (int kc = 0; kc < 4; ++kc) {
                    const int abase = (kc * 4 + kb) * 250 + jofs2;
                    const uint2 p00 = *(const uint2*)(xs + abase + qo0);
                    const uint2 p01 = *(const uint2*)(xs + abase + qo1);
                    const uint2 p10 = *(const uint2*)(xs + WSTRIDE + abase + qo0);
                    const uint2 p11 = *(const uint2*)(xs + WSTRIDE + abase + qo1);
#pragma unroll
                    for (int ntp = 0; ntp < 4; ++ntp) {
                        const uint4 B = bp[(kc * 4 + ntp) * 32];
                        MMA(c[0][2 * ntp][0], c[0][2 * ntp][1], c[0][2 * ntp][2], c[0][2 * ntp][3],
                            p00.x, p01.x, p00.y, p01.y, B.x, B.y);
                        MMA(c[0][2 * ntp + 1][0], c[0][2 * ntp + 1][1], c[0][2 * ntp + 1][2], c[0][2 * ntp + 1][3],
                            p00.x, p01.x, p00.y, p01.y, B.z, B.w);
                        MMA(c[1][2 * ntp][0], c[1][2 * ntp][1], c[1][2 * ntp][2], c[1][2 * ntp][3],
                            p10.x, p11.x, p10.y, p11.y, B.x, B.y);
                        MMA(c[1][2 * ntp + 1][0], c[1][2 * ntp + 1][1], c[1][2 * ntp + 1][2], c[1][2 * ntp + 1][3],
                            p10.x, p11.x, p10.y, p11.y, B.z, B.w);
                    }
                }
            }
        }
    }

#pragma unroll
    for (int w = 0; w < 2; ++w)
#pragma unroll
        for (int nt = 0; nt < 8; ++nt) {
            rmax[w][nt][0] = fmaxf(rmax[w][nt][0], c[w][nt][0]);
            rmax[w][nt][1] = fmaxf(rmax[w][nt][1], c[w][nt][1]);
            if (v1) {
                rmax[w][nt][0] = fmaxf(rmax[w][nt][0], c[w][nt][2]);
                rmax[w][nt][1] = fmaxf(rmax[w][nt][1], c[w][nt][3]);
            }
        }
}

template <int PD0, int PH0, int PW0, int PD1, int PH1, int PW1>
__device__ __forceinline__ void process_pair(
    const float* __restrict__ xs, const int kb, const int lane,
    const int rr, float rmax[2][8][2])
{
    process_half<PD0, PH0, PW0>(xs, kb, lane, rr, 0, rmax);
    process_half<PD0, PH0, PW0>(xs, kb, lane, rr, 1, rmax);
    process_half<PD1, PH1, PW1>(xs, kb, lane, rr, 0, rmax);
    process_half<PD1, PH1, PW1>(xs, kb, lane, rr, 1, rmax);
}

// Patch layout: xs[w][pair(16)][pos(125)][2] floats; pair pc=kc*4+kb holds
// cins (8kc+2kb, 8kc+2kb+1) as (lo,hi) -> one LDS.64 per (a0,a2) / (a1,a3).
__global__ __launch_bounds__(128, 3)
void fused_kernel(const float* __restrict__ x,
                  const float* __restrict__ bias,
                  float* __restrict__ out)
{
    __shared__ float xs[2 * WSTRIDE];
    __shared__ float smax[2][4][64];
    __shared__ float ssum[4];

    const int tid  = threadIdx.x;       // 128 threads = 4 warps
    const int wid  = tid >> 5;
    const int lane = tid & 31;
    const int kb   = lane & 3;
    const int rr   = lane >> 2;

    const int b0 = blockIdx.x * 2;      // two windows per block

    // Stage both patches (tf32-rounded, paired-cin layout), zero-fill halo.
    for (int t = tid; t < 8000; t += 128) {
        const int w  = t / 4000;
        const int rm = t - w * 4000;
        const int cin = rm / 125;
        const int q   = rm - cin * 125;
        const int bb  = b0 + w;
        const int n_  = bb / 500;
        const int r_  = bb % 500;
        const int odc = r_ / 100;
        const int ohc = (r_ / 10) % 10;
        const int owc = r_ % 10;
        const int dl = q / 25, hl = (q / 5) % 5, wl = q % 5;
        const int id = 3 * odc - 1 + dl;
        const int ih = 3 * ohc - 1 + hl;
        const int iw = 3 * owc - 1 + wl;
        float v = 0.f;
        if (id >= 0 && ih >= 0 && iw >= 0)
            v = x[(((n_ * CIN + cin) * 16 + id) << 10) + (ih << 5) + iw];
        xs[w * WSTRIDE + (cin >> 1) * 250 + q * 2 + (cin & 1)] = __uint_as_float(f2tf32(v));
    }
    __syncthreads();

    float rmax[2][8][2];
#pragma unroll
    for (int w = 0; w < 2; ++w)
#pragma unroll
        for (int nt = 0; nt < 8; ++nt) { rmax[w][nt][0] = -INFINITY; rmax[w][nt][1] = -INFINITY; }

    // Balanced class pairs per warp (tap-units incl. both halves):
    //   w0: (0,0,0)+(1,1,1) = 27+8  = 35
    //   w1: (0,0,1)+(0,1,1) = 18+12 = 30
    //   w2: (0,1,0)+(1,0,1) = 18+12 = 30
    //   w3: (1,0,0)+(1,1,0) = 18+12 = 30
    switch (wid) {
        case 0: process_pair<0,0,0, 1,1,1>(xs, kb, lane, rr, rmax); break;
        case 1: process_pair<0,0,1, 0,1,1>(xs, kb, lane, rr, rmax); break;
        case 2: process_pair<0,1,0, 1,0,1>(xs, kb, lane, rr, rmax); break;
        default: process_pair<1,0,0, 1,1,0>(xs, kb, lane, rr, rmax); break;
    }

    // reduce max across row-group lanes (same kb)
#pragma unroll
    for (int o = 4; o < 32; o <<= 1)
#pragma unroll
        for (int w = 0; w < 2; ++w)
#pragma unroll
            for (int nt = 0; nt < 8; ++nt) {
                rmax[w][nt][0] = fmaxf(rmax[w][nt][0], __shfl_xor_sync(0xffffffffu, rmax[w][nt][0], o));
                rmax[w][nt][1] = fmaxf(rmax[w][nt][1], __shfl_xor_sync(0xffffffffu, rmax[w][nt][1], o));
            }
    if (rr == 0) {
#pragma unroll
        for (int w = 0; w < 2; ++w)
#pragma unroll
            for (int nt = 0; nt < 8; ++nt) {
                smax[w][wid][nt * 8 + 2 * kb]     = rmax[w][nt][0];
                smax[w][wid][nt * 8 + 2 * kb + 1] = rmax[w][nt][1];
            }
    }
    __syncthreads();

    // tid 0..63 -> window 0, 64..127 -> window 1; cout = tid&63
    {
        const int w    = tid >> 6;
        const int cout = tid & 63;
        float v = fmaxf(fmaxf(smax[w][0][cout], smax[w][1][cout]),
                        fmaxf(smax[w][2][cout], smax[w][3][cout])) + bias[cout];
#pragma unroll
        for (int o = 16; o > 0; o >>= 1)
            v += __shfl_down_sync(0xffffffffu, v, o);
        if (lane == 0) ssum[tid >> 5] = v;
    }
    __syncthreads();
    if (tid == 0) {
        out[b0]     = ssum[0] + ssum[1];
        out[b0 + 1] = ssum[2] + ssum[3];
    }
}

extern "C" void kernel_launch(void* const* d_in, const int* in_sizes, int n_in,
                              void* d_out, int out_size) {
    const float* x    = (const float*)d_in[0];
    const float* w    = (const float*)d_in[1];
    const float* bias = (const float*)d_in[2];
    float* out = (float*)d_out;

    bf_pack_kernel<<<(125 * 4 * 4 * 32 + 255) / 256, 256>>>(w);
    fused_kernel<<<4000, 128>>>(x, bias, out);
}

// round 10
// speedup vs baseline: 3.0290x; 3.0290x over previous
#include <cuda_runtime.h>
#include <math.h>

#define CIN 32
#define COUT 64
#define WSTRIDE 4000

// Weight B-fragments prepacked in mma.m16n8k8 layout with PERMUTED cin<->k map:
// within kc-block of 8 cins, k -> cin_phys = 2*(k&3) + (k>=4).
// [tap(125)][kc(4)][ntp(4)][lane(32)] uint4 = (b0,b1 @ n-tile 2ntp, b0,b1 @ 2ntp+1)
__device__ uint4 g_bf[125 * 4 * 4 * 32];

__device__ __forceinline__ unsigned f2tf32(float v) {
    unsigned u;
    asm("cvt.rna.tf32.f32 %0, %1;" : "=r"(u) : "f"(v));
    return u;
}

__global__ void bf_pack_kernel(const float* __restrict__ w) {
    int i = blockIdx.x * blockDim.x + threadIdx.x;
    if (i >= 125 * 4 * 4 * 32) return;
    int lane = i & 31, ntp = (i >> 5) & 3, kc = (i >> 7) & 3, tap = i >> 9;
    int k = lane & 3, n = lane >> 2;
    int cinA = kc * 8 + 2 * k;
    int cinB = cinA + 1;
    int cout0 = (2 * ntp) * 8 + n, cout1 = cout0 + 8;
    uint4 o;
    o.x = f2tf32(w[(cinA * COUT + cout0) * 125 + tap]);
    o.y = f2tf32(w[(cinB * COUT + cout0) * 125 + tap]);
    o.z = f2tf32(w[(cinA * COUT + cout1) * 125 + tap]);
    o.w = f2tf32(w[(cinB * COUT + cout1) * 125 + tap]);
    g_bf[i] = o;
}

#define MMA(c0, c1, c2, c3, a0, a1, a2, a3, b0, b1)                              \
    asm("mma.sync.aligned.m16n8k8.row.col.f32.tf32.tf32.f32 "                    \
        "{%0,%1,%2,%3}, {%4,%5,%6,%7}, {%8,%9}, {%0,%1,%2,%3};"                  \
        : "+f"(c0), "+f"(c1), "+f"(c2), "+f"(c3)                                 \
        : "r"(a0), "r"(a1), "r"(a2), "r"(a3), "r"(b0), "r"(b1))

__device__ __forceinline__ int qoff(int pos) {      // pos in [0,27)
    int qd = pos / 9, qh = (pos / 3) % 3, qw = pos % 3;
    return qd * 25 + qh * 5 + qw;
}

// Patch layout: xs[w][pair(16)][pos(125)][2] floats; pair pc=kc*4+kb holds
// cins (8kc+2kb, 8kc+2kb+1) as (lo,hi) -> one LDS.64 per (a0,a2) / (a1,a3).
__global__ __launch_bounds__(128, 3)
void fused_kernel(const float* __restrict__ x,
                  const float* __restrict__ bias,
                  float* __restrict__ out)
{
    __shared__ float xs[2 * WSTRIDE];
    __shared__ int2  stab[8][27];       // per-class tap list: (g_bf uint4-offset, patch f32-offset)
    __shared__ float smax[2][4][64];
    __shared__ float ssum[4];

    const int tid  = threadIdx.x;       // 128 threads = 4 warps
    const int wid  = tid >> 5;
    const int lane = tid & 31;
    const int kb   = lane & 3;
    const int rr   = lane >> 2;

    const int b0 = blockIdx.x * 2;      // two windows per block

    // Build per-class tap tables (8 threads, ~27 iters each; overlaps staging).
    if (tid < 8) {
        const int pd = (tid >> 2) & 1, ph = (tid >> 1) & 1, pw = tid & 1;
        int cnt = 0;
        for (int ia = 0; ia < (pd ? 2 : 3); ++ia) {
            const int kd = pd + 2 * ia, jd = 2 - ia;
            for (int ib = 0; ib < (ph ? 2 : 3); ++ib) {
                const int kh = ph + 2 * ib, jh = 2 - ib;
                for (int ic = 0; ic < (pw ? 2 : 3); ++ic) {
                    const int kw = pw + 2 * ic, jw = 2 - ic;
                    stab[tid][cnt++] = make_int2((kd * 25 + kh * 5 + kw) * 512,
                                                 2 * (jd * 25 + jh * 5 + jw));
                }
            }
        }
    }

    // Stage both patches (tf32-rounded, paired-cin layout), zero-fill halo.
    for (int t = tid; t < 8000; t += 128) {
        const int w  = t / 4000;
        const int rm = t - w * 4000;
        const int cin = rm / 125;
        const int q   = rm - cin * 125;
        const int bb  = b0 + w;
        const int n_  = bb / 500;
        const int r_  = bb % 500;
        const int odc = r_ / 100;
        const int ohc = (r_ / 10) % 10;
        const int owc = r_ % 10;
        const int dl = q / 25, hl = (q / 5) % 5, wl = q % 5;
        const int id = 3 * odc - 1 + dl;
        const int ih = 3 * ohc - 1 + hl;
        const int iw = 3 * owc - 1 + wl;
        float v = 0.f;
        if (id >= 0 && ih >= 0 && iw >= 0)
            v = x[(((n_ * CIN + cin) * 16 + id) << 10) + (ih << 5) + iw];
        xs[w * WSTRIDE + (cin >> 1) * 250 + q * 2 + (cin & 1)] = __uint_as_float(f2tf32(v));
    }
    __syncthreads();

    float rmax[2][8][2];
#pragma unroll
    for (int w = 0; w < 2; ++w)
#pragma unroll
        for (int nt = 0; nt < 8; ++nt) { rmax[w][nt][0] = -INFINITY; rmax[w][nt][1] = -INFINITY; }

    // Balanced schedule: w0 {0,4,3,7}@h0, w1 {0,4,3,7}@h1, w2 {1,2,5,6}@h0, w3 @h1.
    // Tap-units per warp: 65/65/60/60 (vs 75/50 unbalanced).
    const int CLS_TBL[2][4] = {{0, 4, 3, 7}, {1, 2, 5, 6}};
    const int half = wid & 1;

#pragma unroll 1
    for (int s = 0; s < 4; ++s) {
        const int cls = CLS_TBL[wid >> 1][s];
        const int ntaps = ((cls & 4) ? 2 : 3) * ((cls & 2) ? 2 : 3) * ((cls & 1) ? 2 : 3);

        const int pos0 = half * 16 + rr;        // < 27 always
        const int pos1 = pos0 + 8;
        const bool v1  = (pos1 < 27);
        const int qo0 = 2 * qoff(pos0);
        const int qo1 = v1 ? 2 * qoff(pos1) : 0;

        float c[2][8][4];
#pragma unroll
        for (int w = 0; w < 2; ++w)
#pragma unroll
            for (int nt = 0; nt < 8; ++nt)
#pragma unroll
                for (int j = 0; j < 4; ++j) c[w][nt][j] = 0.f;

#pragma unroll 1
        for (int t = 0; t < ntaps; ++t) {
            const int2 e = stab[cls][t];
            const uint4* bp = g_bf + e.x + lane;
#pragma unroll
            for (int kc = 0; kc < 4; ++kc) {
                const int abase = (kc * 4 + kb) * 250 + e.y;
                const uint2 p00 = *(const uint2*)(xs + abase + qo0);
                const uint2 p01 = *(const uint2*)(xs + abase + qo1);
                const uint2 p10 = *(const uint2*)(xs + WSTRIDE + abase + qo0);
                const uint2 p11 = *(const uint2*)(xs + WSTRIDE + abase + qo1);
#pragma unroll
                for (int ntp = 0; ntp < 4; ++ntp) {
                    const uint4 B = bp[(kc * 4 + ntp) * 32];
                    MMA(c[0][2 * ntp][0], c[0][2 * ntp][1], c[0][2 * ntp][2], c[0][2 * ntp][3],
                        p00.x, p01.x, p00.y, p01.y, B.x, B.y);
                    MMA(c[0][2 * ntp + 1][0], c[0][2 * ntp + 1][1], c[0][2 * ntp + 1][2], c[0][2 * ntp + 1][3],
                        p00.x, p01.x, p00.y, p01.y, B.z, B.w);
                    MMA(c[1][2 * ntp][0], c[1][2 * ntp][1], c[1][2 * ntp][2], c[1][2 * ntp][3],
                        p10.x, p11.x, p10.y, p11.y, B.x, B.y);
                    MMA(c[1][2 * ntp + 1][0], c[1][2 * ntp + 1][1], c[1][2 * ntp + 1][2], c[1][2 * ntp + 1][3],
                        p10.x, p11.x, p10.y, p11.y, B.z, B.w);
                }
            }
        }

        // fold max-pool over this m-tile's positions (mask padded rows)
#pragma unroll
        for (int w = 0; w < 2; ++w)
#pragma unroll
            for (int nt = 0; nt < 8; ++nt) {
                rmax[w][nt][0] = fmaxf(rmax[w][nt][0], c[w][nt][0]);
                rmax[w][nt][1] = fmaxf(rmax[w][nt][1], c[w][nt][1]);
                if (v1) {
                    rmax[w][nt][0] = fmaxf(rmax[w][nt][0], c[w][nt][2]);
                    rmax[w][nt][1] = fmaxf(rmax[w][nt][1], c[w][nt][3]);
                }
            }
    }

    // reduce max across row-group lanes (same kb)
#pragma unroll
    for (int o = 4; o < 32; o <<= 1)
#pragma unroll
        for (int w = 0; w < 2; ++w)
#pragma unroll
            for (int nt = 0; nt < 8; ++nt) {
                rmax[w][nt][0] = fmaxf(rmax[w][nt][0], __shfl_xor_sync(0xffffffffu, rmax[w][nt][0], o));
                rmax[w][nt][1] = fmaxf(rmax[w][nt][1], __shfl_xor_sync(0xffffffffu, rmax[w][nt][1], o));
            }
    if (rr == 0) {
#pragma unroll
        for (int w = 0; w < 2; ++w)
#pragma unroll
            for (int nt = 0; nt < 8; ++nt) {
                smax[w][wid][nt * 8 + 2 * kb]     = rmax[w][nt][0];
                smax[w][wid][nt * 8 + 2 * kb + 1] = rmax[w][nt][1];
            }
    }
    __syncthreads();

    // tid 0..63 -> window 0, 64..127 -> window 1; cout = tid&63
    {
        const int w    = tid >> 6;
        const int cout = tid & 63;
        float v = fmaxf(fmaxf(smax[w][0][cout], smax[w][1][cout]),
                        fmaxf(smax[w][2][cout], smax[w][3][cout])) + bias[cout];
#pragma unroll
        for (int o = 16; o > 0; o >>= 1)
            v += __shfl_down_sync(0xffffffffu, v, o);
        if (lane == 0) ssum[tid >> 5] = v;
    }
    __syncthreads();
    if (tid == 0) {
        out[b0]     = ssum[0] + ssum[1];
        out[b0 + 1] = ssum[2] + ssum[3];
    }
}

extern "C" void kernel_launch(void* const* d_in, const int* in_sizes, int n_in,
                              void* d_out, int out_size) {
    const float* x    = (const float*)d_in[0];
    const float* w    = (const float*)d_in[1];
    const float* bias = (const float*)d_in[2];
    float* out = (float*)d_out;

    bf_pack_kernel<<<(125 * 4 * 4 * 32 + 255) / 256, 256>>>(w);
    fused_kernel<<<4000, 128>>>(x, bias, out);
}

// round 11
// speedup vs baseline: 4.3416x; 1.4334x over previous
#include <cuda_runtime.h>
#include <cuda_bf16.h>
#include <math.h>

#define CIN 32
#define COUT 64

// B-fragments for mma.m16n8k16.bf16, prepacked:
// [tap(125)][kc(2)][ntp(4)][lane(32)] uint4 =
//   (.x = {k0,k0+1}@nt 2ntp, .y = {k0+8,k0+9}@nt 2ntp, .z/.w same @nt 2ntp+1)
// where k0 = 2*(lane&3), n = lane>>2, cin = kc*16 + k.
__device__ uint4 g_bf[125 * 2 * 4 * 32];

__device__ __forceinline__ unsigned pack_bf2(float lo, float hi) {
    unsigned r;
    asm("cvt.rn.bf16x2.f32 %0, %1, %2;" : "=r"(r) : "f"(hi), "f"(lo));
    return r;
}

__global__ void bf_pack_kernel(const float* __restrict__ w) {
    int i = blockIdx.x * blockDim.x + threadIdx.x;
    if (i >= 125 * 2 * 4 * 32) return;
    int lane = i & 31, ntp = (i >> 5) & 3, kc = (i >> 7) & 1, tap = i >> 8;
    int k0 = 2 * (lane & 3), n = lane >> 2;
    int cb = kc * 16;
    int cout0 = ntp * 16 + n, cout1 = cout0 + 8;
#define WV(ci, co) w[((ci) * COUT + (co)) * 125 + tap]
    uint4 o;
    o.x = pack_bf2(WV(cb + k0,     cout0), WV(cb + k0 + 1, cout0));
    o.y = pack_bf2(WV(cb + k0 + 8, cout0), WV(cb + k0 + 9, cout0));
    o.z = pack_bf2(WV(cb + k0,     cout1), WV(cb + k0 + 1, cout1));
    o.w = pack_bf2(WV(cb + k0 + 8, cout1), WV(cb + k0 + 9, cout1));
#undef WV
    g_bf[i] = o;
}

#define MMAB(c0, c1, c2, c3, a0, a1, a2, a3, b0, b1)                             \
    asm("mma.sync.aligned.m16n8k16.row.col.f32.bf16.bf16.f32 "                   \
        "{%0,%1,%2,%3}, {%4,%5,%6,%7}, {%8,%9}, {%0,%1,%2,%3};"                  \
        : "+f"(c0), "+f"(c1), "+f"(c2), "+f"(c3)                                 \
        : "r"(a0), "r"(a1), "r"(a2), "r"(a3), "r"(b0), "r"(b1))

__device__ __forceinline__ int qoff(int pos) {      // pos in [0,27)
    int qd = pos / 9, qh = (pos / 3) % 3, qw = pos % 3;
    return qd * 25 + qh * 5 + qw;
}

// A-patch layout: xs[w][kc(2)][kb(4)][q(128 pad)] as uint2:
//   .x = bf16x2 of cins (kc*16+2kb, +1)   -> A reg a0/a1
//   .y = bf16x2 of cins (kc*16+2kb+8, +9) -> A reg a2/a3
__global__ __launch_bounds__(128, 3)
void fused_kernel(const float* __restrict__ x,
                  const float* __restrict__ bias,
                  float* __restrict__ out)
{
    __shared__ uint2 xs[2 * 2 * 4 * 128];   // 16 KB
    __shared__ int2  stab[8][27];           // per-class taps: (g_bf uint4-offset, patch q-offset)
    __shared__ float smax[2][4][64];
    __shared__ float ssum[4];

    const int tid  = threadIdx.x;           // 128 threads = 4 warps
    const int wid  = tid >> 5;
    const int lane = tid & 31;
    const int kb   = lane & 3;
    const int rr   = lane >> 2;

    const int b0 = blockIdx.x * 2;          // two windows per block

    // Build per-class tap tables.
    if (tid < 8) {
        const int pd = (tid >> 2) & 1, ph = (tid >> 1) & 1, pw = tid & 1;
        int cnt = 0;
        for (int ia = 0; ia < (pd ? 2 : 3); ++ia) {
            const int kd = pd + 2 * ia, jd = 2 - ia;
            for (int ib = 0; ib < (ph ? 2 : 3); ++ib) {
                const int kh = ph + 2 * ib, jh = 2 - ib;
                for (int ic = 0; ic < (pw ? 2 : 3); ++ic) {
                    const int kw = pw + 2 * ic, jw = 2 - ic;
                    stab[tid][cnt++] = make_int2((kd * 25 + kh * 5 + kw) * 256,
                                                 jd * 25 + jh * 5 + jw);
                }
            }
        }
    }

    // Stage both patches as bf16, zero-fill halo.
    for (int t = tid; t < 8000; t += 128) {
        const int w  = t / 4000;
        const int rm = t - w * 4000;
        const int cin = rm / 125;
        const int q   = rm - cin * 125;
        const int bb  = b0 + w;
        const int n_  = bb / 500;
        const int r_  = bb % 500;
        const int odc = r_ / 100;
        const int ohc = (r_ / 10) % 10;
        const int owc = r_ % 10;
        const int dl = q / 25, hl = (q / 5) % 5, wl = q % 5;
        const int id = 3 * odc - 1 + dl;
        const int ih = 3 * ohc - 1 + hl;
        const int iw = 3 * owc - 1 + wl;
        float v = 0.f;
        if (id >= 0 && ih >= 0 && iw >= 0)
            v = x[(((n_ * CIN + cin) * 16 + id) << 10) + (ih << 5) + iw];
        // cin -> (kc, kb2, j, parity): cin = kc*16 + 2*(kb2 + 4*j) + parity
        const int kc  = cin >> 4;
        const int rb  = cin & 15;
        const int par = rb & 1;
        const int cp  = rb >> 1;            // cinpair 0..7
        const int kb2 = cp & 3;
        const int j   = cp >> 2;
        const int word = (((w * 2 + kc) * 4 + kb2) * 128 + q) * 2 + j;
        ((__nv_bfloat16*)xs)[word * 2 + par] = __float2bfloat16(v);
    }
    __syncthreads();

    float rmax[2][8][2];
#pragma unroll
    for (int w = 0; w < 2; ++w)
#pragma unroll
        for (int nt = 0; nt < 8; ++nt) { rmax[w][nt][0] = -INFINITY; rmax[w][nt][1] = -INFINITY; }

    // Balanced schedule: w0 {0,4,3,7}@h0, w1 @h1, w2 {1,2,5,6}@h0, w3 @h1.
    const int CLS_TBL[2][4] = {{0, 4, 3, 7}, {1, 2, 5, 6}};
    const int half = wid & 1;

#pragma unroll 1
    for (int s = 0; s < 4; ++s) {
        const int cls = CLS_TBL[wid >> 1][s];
        const int ntaps = ((cls & 4) ? 2 : 3) * ((cls & 2) ? 2 : 3) * ((cls & 1) ? 2 : 3);

        const int pos0 = half * 16 + rr;    // < 27 always
        const int pos1 = pos0 + 8;
        const bool v1  = (pos1 < 27);
        const int qo0 = qoff(pos0);
        const int qo1 = v1 ? qoff(pos1) : 0;

        float c[2][8][4];
#pragma unroll
        for (int w = 0; w < 2; ++w)
#pragma unroll
            for (int nt = 0; nt < 8; ++nt)
#pragma unroll
                for (int j = 0; j < 4; ++j) c[w][nt][j] = 0.f;

#pragma unroll 1
        for (int t = 0; t < ntaps; ++t) {
            const int2 e = stab[cls][t];
            const uint4* bp = g_bf + e.x + lane;
#pragma unroll
            for (int kc = 0; kc < 2; ++kc) {
                const int a0b = (kc * 4 + kb) * 128 + e.y;
                const int a1b = a0b + 4 * 128 * 2;          // window 1 offset (w*2+kc major)
                const uint2 p00 = xs[a0b + qo0];            // w0: (a0, a2)
                const uint2 p01 = xs[a0b + qo1];            // w0: (a1, a3)
                const uint2 p10 = xs[a1b + qo0];            // w1
                const uint2 p11 = xs[a1b + qo1];
#pragma unroll
                for (int ntp = 0; ntp < 4; ++ntp) {
                    const uint4 B = bp[(kc * 4 + ntp) * 32];
                    MMAB(c[0][2 * ntp][0], c[0][2 * ntp][1], c[0][2 * ntp][2], c[0][2 * ntp][3],
                         p00.x, p01.x, p00.y, p01.y, B.x, B.y);
                    MMAB(c[0][2 * ntp + 1][0], c[0][2 * ntp + 1][1], c[0][2 * ntp + 1][2], c[0][2 * ntp + 1][3],
                         p00.x, p01.x, p00.y, p01.y, B.z, B.w);
                    MMAB(c[1][2 * ntp][0], c[1][2 * ntp][1], c[1][2 * ntp][2], c[1][2 * ntp][3],
                         p10.x, p11.x, p10.y, p11.y, B.x, B.y);
                    MMAB(c[1][2 * ntp + 1][0], c[1][2 * ntp + 1][1], c[1][2 * ntp + 1][2], c[1][2 * ntp + 1][3],
                         p10.x, p11.x, p10.y, p11.y, B.z, B.w);
                }
            }
        }

        // fold max-pool over this m-tile's positions (mask padded rows)
#pragma unroll
        for (int w = 0; w < 2; ++w)
#pragma unroll
            for (int nt = 0; nt < 8; ++nt) {
                rmax[w][nt][0] = fmaxf(rmax[w][nt][0], c[w][nt][0]);
                rmax[w][nt][1] = fmaxf(rmax[w][nt][1], c[w][nt][1]);
                if (v1) {
                    rmax[w][nt][0] = fmaxf(rmax[w][nt][0], c[w][nt][2]);
                    rmax[w][nt][1] = fmaxf(rmax[w][nt][1], c[w][nt][3]);
                }
            }
    }

    // reduce max across row-group lanes (same kb)
#pragma unroll
    for (int o = 4; o < 32; o <<= 1)
#pragma unroll
        for (int w = 0; w < 2; ++w)
#pragma unroll
            for (int nt = 0; nt < 8; ++nt) {
                rmax[w][nt][0] = fmaxf(rmax[w][nt][0], __shfl_xor_sync(0xffffffffu, rmax[w][nt][0], o));
                rmax[w][nt][1] = fmaxf(rmax[w][nt][1], __shfl_xor_sync(0xffffffffu, rmax[w][nt][1], o));
            }
    if (rr == 0) {
#pragma unroll
        for (int w = 0; w < 2; ++w)
#pragma unroll
            for (int nt = 0; nt < 8; ++nt) {
                smax[w][wid][nt * 8 + 2 * kb]     = rmax[w][nt][0];
                smax[w][wid][nt * 8 + 2 * kb + 1] = rmax[w][nt][1];
            }
    }
    __syncthreads();

    // tid 0..63 -> window 0, 64..127 -> window 1; cout = tid&63
    {
        const int w    = tid >> 6;
        const int cout = tid & 63;
        float v = fmaxf(fmaxf(smax[w][0][cout], smax[w][1][cout]),
                        fmaxf(smax[w][2][cout], smax[w][3][cout])) + bias[cout];
#pragma unroll
        for (int o = 16; o > 0; o >>= 1)
            v += __shfl_down_sync(0xffffffffu, v, o);
        if (lane == 0) ssum[tid >> 5] = v;
    }
    __syncthreads();
    if (tid == 0) {
        out[b0]     = ssum[0] + ssum[1];
        out[b0 + 1] = ssum[2] + ssum[3];
    }
}

extern "C" void kernel_launch(void* const* d_in, const int* in_sizes, int n_in,
                              void* d_out, int out_size) {
    const float* x    = (const float*)d_in[0];
    const float* w    = (const float*)d_in[1];
    const float* bias = (const float*)d_in[2];
    float* out = (float*)d_out;

    bf_pack_kernel<<<(125 * 2 * 4 * 32 + 255) / 256, 256>>>(w);
    fused_kernel<<<4000, 128>>>(x, bias, out);
}